// round 2
// baseline (speedup 1.0000x reference)
#include <cuda_runtime.h>
#include <cuda_bf16.h>

// Problem constants (fixed shapes from reference setup_inputs)
#define NN    64
#define CC    64
#define HWSZ  16384            // 128*128
#define BINS  32
#define TOTAL (NN * CC * HWSZ) // 67,108,864

// ---------------------------------------------------------------------------
// Global scratch for min/max (no allocations allowed -> __device__ globals).
// Encoded floats so atomicMin/atomicMax on unsigned give float ordering.
// ---------------------------------------------------------------------------
__device__ unsigned int g_min_enc;
__device__ unsigned int g_max_enc;

__device__ __forceinline__ unsigned int enc_f(float f) {
    unsigned int u = __float_as_uint(f);
    return (u & 0x80000000u) ? ~u : (u | 0x80000000u);
}
__device__ __forceinline__ float dec_f(unsigned int u) {
    unsigned int v = (u & 0x80000000u) ? (u & 0x7FFFFFFFu) : ~u;
    return __uint_as_float(v);
}

__global__ void hp_init_kernel() {
    g_min_enc = 0xFFFFFFFFu;  // encodes "+inf" side (max encoded value)
    g_max_enc = 0x00000000u;  // encodes "-inf" side (min encoded value)
}

// ---------------------------------------------------------------------------
// Pass 1: global min/max over 67M floats. HBM-bound (~32us ideal @ 8TB/s).
// 2-deep batched loads for MLP.
// ---------------------------------------------------------------------------
__global__ void __launch_bounds__(256) hp_minmax_kernel(const float4* __restrict__ x4) {
    int tid    = blockIdx.x * blockDim.x + threadIdx.x;
    int stride = gridDim.x * blockDim.x;
    float vmin =  3.402823466e38f;
    float vmax = -3.402823466e38f;

    const int n4 = TOTAL / 4;   // 16,777,216 float4s; grid*block = 524,288 -> 32 iters
    int i = tid;
    for (; i + stride < n4; i += 2 * stride) {
        float4 a = x4[i];
        float4 b = x4[i + stride];
        float lo = fminf(fminf(a.x, a.y), fminf(a.z, a.w));
        float hi = fmaxf(fmaxf(a.x, a.y), fmaxf(a.z, a.w));
        lo = fminf(lo, fminf(fminf(b.x, b.y), fminf(b.z, b.w)));
        hi = fmaxf(hi, fmaxf(fmaxf(b.x, b.y), fmaxf(b.z, b.w)));
        vmin = fminf(vmin, lo);
        vmax = fmaxf(vmax, hi);
    }
    if (i < n4) {
        float4 a = x4[i];
        vmin = fminf(vmin, fminf(fminf(a.x, a.y), fminf(a.z, a.w)));
        vmax = fmaxf(vmax, fmaxf(fmaxf(a.x, a.y), fmaxf(a.z, a.w)));
    }

    // warp reduce
    #pragma unroll
    for (int o = 16; o > 0; o >>= 1) {
        vmin = fminf(vmin, __shfl_xor_sync(0xFFFFFFFFu, vmin, o));
        vmax = fmaxf(vmax, __shfl_xor_sync(0xFFFFFFFFu, vmax, o));
    }

    __shared__ float smin[8], smax[8];
    int warp = threadIdx.x >> 5;
    if ((threadIdx.x & 31) == 0) { smin[warp] = vmin; smax[warp] = vmax; }
    __syncthreads();
    if (threadIdx.x == 0) {
        #pragma unroll
        for (int w = 1; w < 8; w++) {
            vmin = fminf(vmin, smin[w]);
            vmax = fmaxf(vmax, smax[w]);
        }
        atomicMin(&g_min_enc, enc_f(vmin));
        atomicMax(&g_max_enc, enc_f(vmax));
    }
}

// ---------------------------------------------------------------------------
// Pass 2: one block per (n,c) slice (4096 blocks x 256 threads).
// z[n,c] = sum_hw tanh(v) * coeff[c, bin(v)]
//
// bin(v) replicates jnp.searchsorted(linspace(min,max,33), v, 'right')-1,
// clipped to [0,31]:
//   guess b = floor((v-min)*inv_delta), then correct +-1 against
//   tau[b] = rn(min + rn(b * delta)) -- the float sequence linspace uses.
//   tau[32] is irrelevant because of the clip to 31.
//
// tanh(v) = 1 - 2/(exp(2v)+1) with __expf/__fdividef: ~1e-7 abs error,
// 2 MUFU ops/elem instead of the slower accurate-tanhf sequence.
// ---------------------------------------------------------------------------
__global__ void __launch_bounds__(256) hp_main_kernel(const float* __restrict__ x,
                                                      const float* __restrict__ coeff,
                                                      float* __restrict__ out) {
    const int nc = blockIdx.x;            // n*CC + c
    const int c  = nc & (CC - 1);

    __shared__ float s_coeff[BINS];
    if (threadIdx.x < BINS)
        s_coeff[threadIdx.x] = coeff[c * BINS + threadIdx.x];
    __syncthreads();

    const float xmin = dec_f(g_min_enc);
    const float xmax = dec_f(g_max_enc);
    const float delta     = __fdiv_rn(__fsub_rn(xmax, xmin), (float)BINS);
    const float inv_delta = 1.0f / delta;

    const float4* xp = reinterpret_cast<const float4*>(x + (size_t)nc * HWSZ);

    float acc = 0.0f;
    #pragma unroll
    for (int j = 0; j < HWSZ / (256 * 4); j++) {
        float4 v4 = xp[threadIdx.x + j * 256];
        float vs[4] = {v4.x, v4.y, v4.z, v4.w};
        #pragma unroll
        for (int k = 0; k < 4; k++) {
            float v = vs[k];
            // bin guess
            float r = __fmul_rn(__fsub_rn(v, xmin), inv_delta);
            int b = (int)r;               // r >= 0, trunc == floor
            if (b > BINS - 1) b = BINS - 1;
            // +-1 correction against exact linspace edges
            float tb = __fadd_rn(xmin, __fmul_rn((float)b, delta));
            if (v < tb) {
                b--;
            } else {
                float tb1 = __fadd_rn(xmin, __fmul_rn((float)(b + 1), delta));
                if (b < BINS - 1 && v >= tb1) b++;
            }
            if (b < 0) b = 0;             // safety (v >= xmin = tau[0])
            // tanh via expf: handles large |v| correctly (e=inf -> th=1)
            float e  = __expf(v + v);
            float th = 1.0f - __fdividef(2.0f, e + 1.0f);
            acc = fmaf(th, s_coeff[b], acc);
        }
    }

    // block reduce acc
    #pragma unroll
    for (int o = 16; o > 0; o >>= 1)
        acc += __shfl_xor_sync(0xFFFFFFFFu, acc, o);

    __shared__ float swarp[8];
    int warp = threadIdx.x >> 5;
    if ((threadIdx.x & 31) == 0) swarp[warp] = acc;
    __syncthreads();
    if (threadIdx.x == 0) {
        float t = swarp[0];
        #pragma unroll
        for (int w = 1; w < 8; w++) t += swarp[w];
        out[nc] = t;
    }
}

// ---------------------------------------------------------------------------
extern "C" void kernel_launch(void* const* d_in, const int* in_sizes, int n_in,
                              void* d_out, int out_size) {
    const float* x     = (const float*)d_in[0];
    const float* coeff = (const float*)d_in[1];
    float*       out   = (float*)d_out;

    hp_init_kernel<<<1, 1>>>();
    hp_minmax_kernel<<<2048, 256>>>(reinterpret_cast<const float4*>(x));
    hp_main_kernel<<<NN * CC, 256>>>(x, coeff, out);
}

// round 3
// speedup vs baseline: 1.1039x; 1.1039x over previous
#include <cuda_runtime.h>
#include <cuda_bf16.h>

#define NN    64
#define CC    64
#define HWSZ  16384            // 128*128
#define BINS  32
#define TOTAL (NN * CC * HWSZ) // 67,108,864

// ---------------------------------------------------------------------------
// Global scratch (no allocations allowed). Encoded-uint min/max cells are
// self-resetting: last pass-1 block decodes them into g_min_f/g_max_f and
// restores the init values + counter, so graph replays are deterministic.
// ---------------------------------------------------------------------------
#define ENC_MIN_INIT 0xFFFFFFFFu
#define ENC_MAX_INIT 0x00000000u
__device__ unsigned int g_min_enc = ENC_MIN_INIT;
__device__ unsigned int g_max_enc = ENC_MAX_INIT;
__device__ unsigned int g_count   = 0;
__device__ float        g_min_f, g_max_f;

__device__ __forceinline__ unsigned int enc_f(float f) {
    unsigned int u = __float_as_uint(f);
    return (u & 0x80000000u) ? ~u : (u | 0x80000000u);
}
__device__ __forceinline__ float dec_f(unsigned int u) {
    unsigned int v = (u & 0x80000000u) ? (u & 0x7FFFFFFFu) : ~u;
    return __uint_as_float(v);
}

// ---------------------------------------------------------------------------
// Pass 1: global min/max over 67M floats. HBM-bound (~35us).
// ---------------------------------------------------------------------------
#define MM_GRID 2048
__global__ void __launch_bounds__(256) hp_minmax_kernel(const float4* __restrict__ x4) {
    int tid    = blockIdx.x * blockDim.x + threadIdx.x;
    int stride = gridDim.x * blockDim.x;
    float vmin =  3.402823466e38f;
    float vmax = -3.402823466e38f;

    const int n4 = TOTAL / 4;
    int i = tid;
    for (; i + stride < n4; i += 2 * stride) {
        float4 a = x4[i];
        float4 b = x4[i + stride];
        float lo = fminf(fminf(a.x, a.y), fminf(a.z, a.w));
        float hi = fmaxf(fmaxf(a.x, a.y), fmaxf(a.z, a.w));
        lo = fminf(lo, fminf(fminf(b.x, b.y), fminf(b.z, b.w)));
        hi = fmaxf(hi, fmaxf(fmaxf(b.x, b.y), fmaxf(b.z, b.w)));
        vmin = fminf(vmin, lo);
        vmax = fmaxf(vmax, hi);
    }
    if (i < n4) {
        float4 a = x4[i];
        vmin = fminf(vmin, fminf(fminf(a.x, a.y), fminf(a.z, a.w)));
        vmax = fmaxf(vmax, fmaxf(fmaxf(a.x, a.y), fmaxf(a.z, a.w)));
    }

    #pragma unroll
    for (int o = 16; o > 0; o >>= 1) {
        vmin = fminf(vmin, __shfl_xor_sync(0xFFFFFFFFu, vmin, o));
        vmax = fmaxf(vmax, __shfl_xor_sync(0xFFFFFFFFu, vmax, o));
    }

    __shared__ float smin[8], smax[8];
    __shared__ bool  s_last;
    int warp = threadIdx.x >> 5;
    if ((threadIdx.x & 31) == 0) { smin[warp] = vmin; smax[warp] = vmax; }
    __syncthreads();
    if (threadIdx.x == 0) {
        #pragma unroll
        for (int w = 1; w < 8; w++) {
            vmin = fminf(vmin, smin[w]);
            vmax = fmaxf(vmax, smax[w]);
        }
        atomicMin(&g_min_enc, enc_f(vmin));
        atomicMax(&g_max_enc, enc_f(vmax));
        __threadfence();
        s_last = (atomicAdd(&g_count, 1u) == (unsigned)(gridDim.x - 1));
    }
    __syncthreads();
    if (s_last && threadIdx.x == 0) {
        // finalize + reset for the next graph replay
        g_min_f = dec_f(g_min_enc);
        g_max_f = dec_f(g_max_enc);
        __threadfence();
        g_min_enc = ENC_MIN_INIT;
        g_max_enc = ENC_MAX_INIT;
        g_count   = 0;
    }
}

// ---------------------------------------------------------------------------
// Pass 2: one block per (n,c) slice. z[n,c] = sum_hw tanh(v)*coeff[c,bin(v)].
//
// bin(v) == clip(searchsorted(linspace(min,max,33), v, 'right')-1, 0, 31).
// Fast path: b = trunc((v-xmin)*inv_delta) is provably correct whenever the
// fractional part is > EPS away from 0/1 (guess error is a few ulp ~1e-5 in
// r-space). Slow path (rare) does the exact +-1 correction against
// tau[b] = rn(xmin + rn(b*delta)).
//
// coeff lookup: lane i holds coeff[c,i] in a register; per-element lookup is
// one conflict-free SHFL.IDX instead of a bank-conflicted LDS gather.
// ---------------------------------------------------------------------------
__global__ void __launch_bounds__(256) hp_main_kernel(const float* __restrict__ x,
                                                      const float* __restrict__ coeff,
                                                      float* __restrict__ out) {
    const int nc = blockIdx.x;            // n*CC + c
    const int c  = nc & (CC - 1);

    const float co_lane = coeff[c * BINS + (threadIdx.x & 31)];

    const float xmin = g_min_f;
    const float xmax = g_max_f;
    const float delta     = __fdiv_rn(__fsub_rn(xmax, xmin), (float)BINS);
    const float inv_delta = 1.0f / delta;
    const float EPS = 1.0e-3f;

    const float4* xp = reinterpret_cast<const float4*>(x + (size_t)nc * HWSZ);

    float acc = 0.0f;
    #pragma unroll 4
    for (int j = 0; j < HWSZ / (256 * 4); j++) {
        float4 v4 = xp[threadIdx.x + j * 256];
        float vs[4] = {v4.x, v4.y, v4.z, v4.w};
        #pragma unroll
        for (int k = 0; k < 4; k++) {
            float v = vs[k];
            float r = __fmul_rn(__fsub_rn(v, xmin), inv_delta);  // r in [0, 32+eps]
            int   b = (int)r;                                    // trunc == floor (r>=0)
            float d = r - (float)b;
            if (b > BINS - 1) b = BINS - 1;
            if (d < EPS || d > 1.0f - EPS) {
                // exact correction against linspace edges (rare)
                float tb = __fadd_rn(xmin, __fmul_rn((float)b, delta));
                if (v < tb) {
                    b--;
                } else if (b < BINS - 1) {
                    float tb1 = __fadd_rn(xmin, __fmul_rn((float)(b + 1), delta));
                    if (v >= tb1) b++;
                }
                if (b < 0) b = 0;
            }
            float co = __shfl_sync(0xFFFFFFFFu, co_lane, b);
            // tanh via expf: 2 MUFU, ~1e-7 abs error, inf-safe
            float e  = __expf(v + v);
            float th = 1.0f - __fdividef(2.0f, e + 1.0f);
            acc = fmaf(th, co, acc);
        }
    }

    // block reduce
    #pragma unroll
    for (int o = 16; o > 0; o >>= 1)
        acc += __shfl_xor_sync(0xFFFFFFFFu, acc, o);

    __shared__ float swarp[8];
    int warp = threadIdx.x >> 5;
    if ((threadIdx.x & 31) == 0) swarp[warp] = acc;
    __syncthreads();
    if (threadIdx.x == 0) {
        float t = swarp[0];
        #pragma unroll
        for (int w = 1; w < 8; w++) t += swarp[w];
        out[nc] = t;
    }
}

// ---------------------------------------------------------------------------
extern "C" void kernel_launch(void* const* d_in, const int* in_sizes, int n_in,
                              void* d_out, int out_size) {
    const float* x     = (const float*)d_in[0];
    const float* coeff = (const float*)d_in[1];
    float*       out   = (float*)d_out;

    hp_minmax_kernel<<<MM_GRID, 256>>>(reinterpret_cast<const float4*>(x));
    hp_main_kernel<<<NN * CC, 256>>>(x, coeff, out);
}

// round 4
// speedup vs baseline: 1.2072x; 1.0936x over previous
#include <cuda_runtime.h>
#include <cuda_bf16.h>

#define NN    64
#define CC    64
#define HWSZ  16384            // 128*128
#define BINS  32
#define TOTAL (NN * CC * HWSZ) // 67,108,864

// ---------------------------------------------------------------------------
// Global scratch (no allocations allowed). Encoded-uint min/max cells are
// self-resetting: last pass-1 block decodes into g_min_f/g_max_f and restores
// init values + counter, so graph replays are deterministic.
// ---------------------------------------------------------------------------
#define ENC_MIN_INIT 0xFFFFFFFFu
#define ENC_MAX_INIT 0x00000000u
__device__ unsigned int g_min_enc = ENC_MIN_INIT;
__device__ unsigned int g_max_enc = ENC_MAX_INIT;
__device__ unsigned int g_count   = 0;
__device__ float        g_min_f, g_max_f;

__device__ __forceinline__ unsigned int enc_f(float f) {
    unsigned int u = __float_as_uint(f);
    return (u & 0x80000000u) ? ~u : (u | 0x80000000u);
}
__device__ __forceinline__ float dec_f(unsigned int u) {
    unsigned int v = (u & 0x80000000u) ? (u & 0x7FFFFFFFu) : ~u;
    return __uint_as_float(v);
}

// ---------------------------------------------------------------------------
// Pass 1: global min/max over 67M floats. DRAM-bound (~35us floor).
// 4-deep batched float4 loads for MLP.
// ---------------------------------------------------------------------------
#define MM_GRID 2048
__global__ void __launch_bounds__(256) hp_minmax_kernel(const float4* __restrict__ x4) {
    int tid    = blockIdx.x * blockDim.x + threadIdx.x;
    int stride = gridDim.x * blockDim.x;
    float vmin =  3.402823466e38f;
    float vmax = -3.402823466e38f;

    const int n4 = TOTAL / 4;   // 16,777,216 ; 32 iters/thread at this grid
    int i = tid;
    for (; i + 3 * stride < n4; i += 4 * stride) {
        float4 a = x4[i];
        float4 b = x4[i + stride];
        float4 e = x4[i + 2 * stride];
        float4 f = x4[i + 3 * stride];
        float lo0 = fminf(fminf(a.x, a.y), fminf(a.z, a.w));
        float lo1 = fminf(fminf(b.x, b.y), fminf(b.z, b.w));
        float lo2 = fminf(fminf(e.x, e.y), fminf(e.z, e.w));
        float lo3 = fminf(fminf(f.x, f.y), fminf(f.z, f.w));
        float hi0 = fmaxf(fmaxf(a.x, a.y), fmaxf(a.z, a.w));
        float hi1 = fmaxf(fmaxf(b.x, b.y), fmaxf(b.z, b.w));
        float hi2 = fmaxf(fmaxf(e.x, e.y), fmaxf(e.z, e.w));
        float hi3 = fmaxf(fmaxf(f.x, f.y), fmaxf(f.z, f.w));
        vmin = fminf(vmin, fminf(fminf(lo0, lo1), fminf(lo2, lo3)));
        vmax = fmaxf(vmax, fmaxf(fmaxf(hi0, hi1), fmaxf(hi2, hi3)));
    }
    for (; i < n4; i += stride) {
        float4 a = x4[i];
        vmin = fminf(vmin, fminf(fminf(a.x, a.y), fminf(a.z, a.w)));
        vmax = fmaxf(vmax, fmaxf(fmaxf(a.x, a.y), fmaxf(a.z, a.w)));
    }

    #pragma unroll
    for (int o = 16; o > 0; o >>= 1) {
        vmin = fminf(vmin, __shfl_xor_sync(0xFFFFFFFFu, vmin, o));
        vmax = fmaxf(vmax, __shfl_xor_sync(0xFFFFFFFFu, vmax, o));
    }

    __shared__ float smin[8], smax[8];
    __shared__ bool  s_last;
    int warp = threadIdx.x >> 5;
    if ((threadIdx.x & 31) == 0) { smin[warp] = vmin; smax[warp] = vmax; }
    __syncthreads();
    if (threadIdx.x == 0) {
        #pragma unroll
        for (int w = 1; w < 8; w++) {
            vmin = fminf(vmin, smin[w]);
            vmax = fmaxf(vmax, smax[w]);
        }
        atomicMin(&g_min_enc, enc_f(vmin));
        atomicMax(&g_max_enc, enc_f(vmax));
        __threadfence();
        s_last = (atomicAdd(&g_count, 1u) == (unsigned)(gridDim.x - 1));
    }
    __syncthreads();
    if (s_last && threadIdx.x == 0) {
        g_min_f = dec_f(g_min_enc);
        g_max_f = dec_f(g_max_enc);
        __threadfence();
        g_min_enc = ENC_MIN_INIT;
        g_max_enc = ENC_MAX_INIT;
        g_count   = 0;
    }
}

// ---------------------------------------------------------------------------
// Exact bin: replicate clip(searchsorted(linspace edges, v, 'right')-1, 0, 31)
// against tau[b] = rn(xmin + rn(b*delta)) — only for edge-ambiguous elements.
// ---------------------------------------------------------------------------
__device__ __forceinline__ int bin_exact(float v, float xmin, float delta) {
    float r = (v - xmin) / delta;
    int b = (int)fminf(r, 31.0f);
    float tb = __fadd_rn(xmin, __fmul_rn((float)b, delta));
    if (v < tb) {
        b--;
    } else if (b < BINS - 1) {
        float tb1 = __fadd_rn(xmin, __fmul_rn((float)(b + 1), delta));
        if (v >= tb1) b++;
    }
    return b < 0 ? 0 : b;
}

// ---------------------------------------------------------------------------
// Pass 2: one block per (n,c) slice. z[n,c] = sum_hw tanh(v)*coeff[c,bin(v)].
// Fast bin guess = trunc(fma(v, inv_delta, -xmin*inv_delta)); slow exact path
// taken once per float4 group iff ANY of the 4 fracs is within EPS of an edge
// (disagreement window ~2e-5 in r-space; EPS=2e-4 gives 10x margin).
// coeff lookup via register SHFL.IDX (conflict-free). tanh via MUFU.TANH.
// ---------------------------------------------------------------------------
__global__ void __launch_bounds__(256) hp_main_kernel(const float* __restrict__ x,
                                                      const float* __restrict__ coeff,
                                                      float* __restrict__ out) {
    const int nc = blockIdx.x;            // n*CC + c
    const int c  = nc & (CC - 1);

    const float co_lane = coeff[c * BINS + (threadIdx.x & 31)];

    const float xmin = g_min_f;
    const float xmax = g_max_f;
    const float delta     = __fdiv_rn(__fsub_rn(xmax, xmin), (float)BINS);
    const float inv_delta = 1.0f / delta;
    const float c0        = -xmin * inv_delta;
    const float EPS_THR   = 0.5f - 2.0e-4f;   // |frac-0.5| > this => near edge

    const float4* xp = reinterpret_cast<const float4*>(x + (size_t)nc * HWSZ);

    float acc = 0.0f;
    #pragma unroll 4
    for (int j = 0; j < HWSZ / (256 * 4); j++) {
        float4 v4 = xp[threadIdx.x + j * 256];
        float vs[4] = {v4.x, v4.y, v4.z, v4.w};
        int   bs[4];
        bool  fix = false;
        #pragma unroll
        for (int k = 0; k < 4; k++) {
            float r = fmaf(vs[k], inv_delta, c0);
            int   b = (int)r;                 // trunc == floor (r >= -tiny)
            float d = r - (float)b;
            if (b > BINS - 1) b = BINS - 1;
            bs[k] = b;
            fix = fix || (fabsf(d - 0.5f) > EPS_THR);
        }
        if (fix) {                            // rare: exact edge resolution
            #pragma unroll
            for (int k = 0; k < 4; k++)
                bs[k] = bin_exact(vs[k], xmin, delta);
        }
        #pragma unroll
        for (int k = 0; k < 4; k++) {
            float co = __shfl_sync(0xFFFFFFFFu, co_lane, bs[k]);
            float th;
            asm("tanh.approx.f32 %0, %1;" : "=f"(th) : "f"(vs[k]));
            acc = fmaf(th, co, acc);
        }
    }

    // block reduce
    #pragma unroll
    for (int o = 16; o > 0; o >>= 1)
        acc += __shfl_xor_sync(0xFFFFFFFFu, acc, o);

    __shared__ float swarp[8];
    int warp = threadIdx.x >> 5;
    if ((threadIdx.x & 31) == 0) swarp[warp] = acc;
    __syncthreads();
    if (threadIdx.x == 0) {
        float t = swarp[0];
        #pragma unroll
        for (int w = 1; w < 8; w++) t += swarp[w];
        out[nc] = t;
    }
}

// ---------------------------------------------------------------------------
extern "C" void kernel_launch(void* const* d_in, const int* in_sizes, int n_in,
                              void* d_out, int out_size) {
    const float* x     = (const float*)d_in[0];
    const float* coeff = (const float*)d_in[1];
    float*       out   = (float*)d_out;

    hp_minmax_kernel<<<MM_GRID, 256>>>(reinterpret_cast<const float4*>(x));
    hp_main_kernel<<<NN * CC, 256>>>(x, coeff, out);
}

// round 6
// speedup vs baseline: 1.3495x; 1.1179x over previous
#include <cuda_runtime.h>
#include <cuda_bf16.h>

#define NN    64
#define CC    64
#define HWSZ  16384            // 128*128
#define BINS  32
#define TOTAL (NN * CC * HWSZ) // 67,108,864

// ---------------------------------------------------------------------------
// Global scratch (no allocations allowed). Self-resetting min/max cells:
// last pass-1 block decodes into g_min_f/g_max_f and restores init values,
// so graph replays are deterministic.
// ---------------------------------------------------------------------------
#define ENC_MIN_INIT 0xFFFFFFFFu
#define ENC_MAX_INIT 0x00000000u
__device__ unsigned int g_min_enc = ENC_MIN_INIT;
__device__ unsigned int g_max_enc = ENC_MAX_INIT;
__device__ unsigned int g_count   = 0;
__device__ float        g_min_f, g_max_f;

__device__ __forceinline__ unsigned int enc_f(float f) {
    unsigned int u = __float_as_uint(f);
    return (u & 0x80000000u) ? ~u : (u | 0x80000000u);
}
__device__ __forceinline__ float dec_f(unsigned int u) {
    unsigned int v = (u & 0x80000000u) ? (u & 0x7FFFFFFFu) : ~u;
    return __uint_as_float(v);
}

// ---------------------------------------------------------------------------
// Pass 1: global min/max. DESCENDING grid-stride walk so the LOW half of x is
// L2-resident when this kernel finishes -> pass 2's first-wave blocks (low
// slices) hit L2 instead of DRAM (saves ~100+ MB of DRAM traffic).
// MM_GRID*256*32 float4s == TOTAL/4 exactly (no remainder loop).
// ---------------------------------------------------------------------------
#define MM_GRID 2048
__global__ void __launch_bounds__(256) hp_minmax_kernel(const float4* __restrict__ x4) {
    const int tid    = blockIdx.x * blockDim.x + threadIdx.x;
    const int stride = MM_GRID * 256;          // 524,288 ; n4 = 32*stride exactly
    float vmin =  3.402823466e38f;
    float vmax = -3.402823466e38f;

    #pragma unroll 1
    for (int k = 28; k >= 0; k -= 4) {         // stripes high -> low
        const int i = tid + k * stride;
        float4 a = x4[i];
        float4 b = x4[i + stride];
        float4 e = x4[i + 2 * stride];
        float4 f = x4[i + 3 * stride];
        float lo0 = fminf(fminf(a.x, a.y), fminf(a.z, a.w));
        float lo1 = fminf(fminf(b.x, b.y), fminf(b.z, b.w));
        float lo2 = fminf(fminf(e.x, e.y), fminf(e.z, e.w));
        float lo3 = fminf(fminf(f.x, f.y), fminf(f.z, f.w));
        float hi0 = fmaxf(fmaxf(a.x, a.y), fmaxf(a.z, a.w));
        float hi1 = fmaxf(fmaxf(b.x, b.y), fmaxf(b.z, b.w));
        float hi2 = fmaxf(fmaxf(e.x, e.y), fmaxf(e.z, e.w));
        float hi3 = fmaxf(fmaxf(f.x, f.y), fmaxf(f.z, f.w));
        vmin = fminf(vmin, fminf(fminf(lo0, lo1), fminf(lo2, lo3)));
        vmax = fmaxf(vmax, fmaxf(fmaxf(hi0, hi1), fmaxf(hi2, hi3)));
    }

    #pragma unroll
    for (int o = 16; o > 0; o >>= 1) {
        vmin = fminf(vmin, __shfl_xor_sync(0xFFFFFFFFu, vmin, o));
        vmax = fmaxf(vmax, __shfl_xor_sync(0xFFFFFFFFu, vmax, o));
    }

    __shared__ float smin[8], smax[8];
    __shared__ bool  s_last;
    int warp = threadIdx.x >> 5;
    if ((threadIdx.x & 31) == 0) { smin[warp] = vmin; smax[warp] = vmax; }
    __syncthreads();
    if (threadIdx.x == 0) {
        #pragma unroll
        for (int w = 1; w < 8; w++) {
            vmin = fminf(vmin, smin[w]);
            vmax = fmaxf(vmax, smax[w]);
        }
        atomicMin(&g_min_enc, enc_f(vmin));
        atomicMax(&g_max_enc, enc_f(vmax));
        __threadfence();
        s_last = (atomicAdd(&g_count, 1u) == (unsigned)(gridDim.x - 1));
    }
    __syncthreads();
    if (s_last && threadIdx.x == 0) {
        g_min_f = dec_f(g_min_enc);
        g_max_f = dec_f(g_max_enc);
        __threadfence();
        g_min_enc = ENC_MIN_INIT;
        g_max_enc = ENC_MAX_INIT;
        g_count   = 0;
    }
}

// ---------------------------------------------------------------------------
// Exact bin (rare path): clip(searchsorted(linspace edges, v,'right')-1,0,31)
// against tau[b] = rn(xmin + rn(b*delta)).
// ---------------------------------------------------------------------------
__device__ __forceinline__ int bin_exact(float v, float xmin, float delta) {
    float r = (v - xmin) / delta;
    int b = (int)fminf(r, 31.0f);
    float tb = __fadd_rn(xmin, __fmul_rn((float)b, delta));
    if (v < tb) {
        b--;
    } else if (b < BINS - 1) {
        float tb1 = __fadd_rn(xmin, __fmul_rn((float)(b + 1), delta));
        if (v >= tb1) b++;
    }
    return b < 0 ? 0 : b;
}

// ---------------------------------------------------------------------------
// Pass 2: one block per (n,c) slice. z[n,c] = sum_hw tanh(v)*coeff[c,bin(v)].
//
// Fast bin: magic-number float->int (all 4-cycle FADD/IADD ops, no cvt pipe):
//   r  = fma(v, inv_delta, c0)
//   f  = r + 1.5*2^23            -> rintf(r) in mantissa bits
//   bi = bits(f) - 0x4B400000    -> (int)rintf(r)
//   d  = r - (f - MAGIC)         -> exact frac offset in [-0.5, 0.5]
//   b  = bi - (d < 0)            -> floor(r)
// Edge-ambiguous (|d| < 1e-4, ~30x margin over the fast/exact disagreement
// window) resolved warp-uniformly via __any_sync + exact recompute.
// Out-of-range fast b only occurs on near-edge lanes, which the exact path
// overwrites (SHFL idx is mod-32-safe in the meantime).
// coeff lookup: register SHFL.IDX; tanh: MUFU.TANH.
// ---------------------------------------------------------------------------
__global__ void __launch_bounds__(256, 6) hp_main_kernel(const float* __restrict__ x,
                                                         const float* __restrict__ coeff,
                                                         float* __restrict__ out) {
    const int nc = blockIdx.x;            // n*CC + c
    const int c  = nc & (CC - 1);

    const float co_lane = coeff[c * BINS + (threadIdx.x & 31)];

    const float xmin = g_min_f;
    const float xmax = g_max_f;
    const float delta     = __fdiv_rn(__fsub_rn(xmax, xmin), (float)BINS);
    const float inv_delta = 1.0f / delta;
    const float c0        = -xmin * inv_delta;
    const float MAGIC     = 12582912.0f;  // 1.5 * 2^23
    const float EPS       = 1.0e-4f;

    const float4* xp = reinterpret_cast<const float4*>(x + (size_t)nc * HWSZ);

    float acc = 0.0f;
    #pragma unroll 4
    for (int j = 0; j < HWSZ / (256 * 4); j += 2) {
        float4 a  = xp[threadIdx.x + j * 256];
        float4 b4 = xp[threadIdx.x + (j + 1) * 256];
        float vs[8] = {a.x, a.y, a.z, a.w, b4.x, b4.y, b4.z, b4.w};
        int   bs[8];
        bool  nearEdge = false;
        #pragma unroll
        for (int k = 0; k < 8; k++) {
            float r  = fmaf(vs[k], inv_delta, c0);
            float f  = r + MAGIC;
            int   bi = __float_as_int(f) - 0x4B400000;
            float d  = r - (f - MAGIC);
            bs[k] = (d < 0.0f) ? bi - 1 : bi;     // floor(r)
            nearEdge = nearEdge || (fabsf(d) < EPS);
        }
        if (__any_sync(0xFFFFFFFFu, nearEdge)) {  // rare, warp-uniform
            #pragma unroll
            for (int k = 0; k < 8; k++)
                bs[k] = bin_exact(vs[k], xmin, delta);
        }
        #pragma unroll
        for (int k = 0; k < 8; k++) {
            float co = __shfl_sync(0xFFFFFFFFu, co_lane, bs[k]);
            float th;
            asm("tanh.approx.f32 %0, %1;" : "=f"(th) : "f"(vs[k]));
            acc = fmaf(th, co, acc);
        }
    }

    // block reduce
    #pragma unroll
    for (int o = 16; o > 0; o >>= 1)
        acc += __shfl_xor_sync(0xFFFFFFFFu, acc, o);

    __shared__ float swarp[8];
    int warp = threadIdx.x >> 5;
    if ((threadIdx.x & 31) == 0) swarp[warp] = acc;
    __syncthreads();
    if (threadIdx.x == 0) {
        float t = swarp[0];
        #pragma unroll
        for (int w = 1; w < 8; w++) t += swarp[w];
        out[nc] = t;
    }
}

// ---------------------------------------------------------------------------
extern "C" void kernel_launch(void* const* d_in, const int* in_sizes, int n_in,
                              void* d_out, int out_size) {
    const float* x     = (const float*)d_in[0];
    const float* coeff = (const float*)d_in[1];
    float*       out   = (float*)d_out;

    hp_minmax_kernel<<<MM_GRID, 256>>>(reinterpret_cast<const float4*>(x));
    hp_main_kernel<<<NN * CC, 256>>>(x, coeff, out);
}

// round 10
// speedup vs baseline: 1.3777x; 1.0209x over previous
#include <cuda_runtime.h>
#include <cuda_bf16.h>

#define NN    64
#define CC    64
#define HWSZ  16384            // 128*128
#define BINS  32
#define TOTAL (NN * CC * HWSZ) // 67,108,864
#define N4    (TOTAL / 4)      // 16,777,216 float4s

#define GRID_X   888           // 148 SMs * 6 CTAs -- ALL co-resident (barrier-safe)
#define BLOCK_X  256
#define STRIDE4  (GRID_X * BLOCK_X)   // 227,328

// ---------------------------------------------------------------------------
// Global scratch (no allocations allowed). Self-resetting across graph
// replays: the barrier releaser finalizes min/max, resets the encoded cells
// and the arrival count, then bumps the monotonically-increasing generation.
// ---------------------------------------------------------------------------
#define ENC_MIN_INIT 0xFFFFFFFFu
#define ENC_MAX_INIT 0x00000000u
__device__ unsigned int g_min_enc = ENC_MIN_INIT;
__device__ unsigned int g_max_enc = ENC_MAX_INIT;
__device__ unsigned int g_count   = 0;
__device__ unsigned int g_gen     = 0;
__device__ float        g_min_f, g_max_f;

__device__ __forceinline__ unsigned int enc_f(float f) {
    unsigned int u = __float_as_uint(f);
    return (u & 0x80000000u) ? ~u : (u | 0x80000000u);
}
__device__ __forceinline__ float dec_f(unsigned int u) {
    unsigned int v = (u & 0x80000000u) ? (u & 0x7FFFFFFFu) : ~u;
    return __uint_as_float(v);
}

// ---------------------------------------------------------------------------
// Exact bin (rare path): clip(searchsorted(linspace edges, v,'right')-1,0,31)
// against tau[b] = rn(xmin + rn(b*delta)).
// ---------------------------------------------------------------------------
__device__ __forceinline__ int bin_exact(float v, float xmin, float delta) {
    float r = (v - xmin) / delta;
    int b = (int)fminf(r, 31.0f);
    float tb = __fadd_rn(xmin, __fmul_rn((float)b, delta));
    if (v < tb) {
        b--;
    } else if (b < BINS - 1) {
        float tb1 = __fadd_rn(xmin, __fmul_rn((float)(b + 1), delta));
        if (v >= tb1) b++;
    }
    return b < 0 ? 0 : b;
}

// ---------------------------------------------------------------------------
// Fused persistent kernel.
// Phase 1: descending grid-stride min/max (low addresses end up L2-hot).
// Device-wide barrier (all 888 CTAs resident by construction).
// Phase 2: grid-stride over (n,c) slices; first wave (slices 0..887 = 56MB)
// hits L2 from phase 1's tail.
// ---------------------------------------------------------------------------
__global__ void __launch_bounds__(BLOCK_X, 6)
hp_fused_kernel(const float* __restrict__ x,
                const float* __restrict__ coeff,
                float* __restrict__ out) {
    const int tid  = threadIdx.x;
    const int gtid = blockIdx.x * BLOCK_X + tid;
    const float4* x4 = reinterpret_cast<const float4*>(x);

    __shared__ float s_red[8];
    __shared__ float s_min, s_max;

    // ---------------- Phase 1: min/max, descending walk ----------------
    {
        float mn0 =  3.402823466e38f, mn1 =  3.402823466e38f;
        float mx0 = -3.402823466e38f, mx1 = -3.402823466e38f;

        int i = N4 - STRIDE4 + gtid;           // top stripe
        for (; i >= 3 * STRIDE4; i -= 4 * STRIDE4) {
            float4 a = x4[i];
            float4 b = x4[i -     STRIDE4];
            float4 e = x4[i - 2 * STRIDE4];
            float4 f = x4[i - 3 * STRIDE4];
            mn0 = fminf(mn0, fminf(fminf(a.x, a.y), fminf(a.z, a.w)));
            mx0 = fmaxf(mx0, fmaxf(fmaxf(a.x, a.y), fmaxf(a.z, a.w)));
            mn1 = fminf(mn1, fminf(fminf(b.x, b.y), fminf(b.z, b.w)));
            mx1 = fmaxf(mx1, fmaxf(fmaxf(b.x, b.y), fmaxf(b.z, b.w)));
            mn0 = fminf(mn0, fminf(fminf(e.x, e.y), fminf(e.z, e.w)));
            mx0 = fmaxf(mx0, fmaxf(fmaxf(e.x, e.y), fmaxf(e.z, e.w)));
            mn1 = fminf(mn1, fminf(fminf(f.x, f.y), fminf(f.z, f.w)));
            mx1 = fmaxf(mx1, fmaxf(fmaxf(f.x, f.y), fmaxf(f.z, f.w)));
        }
        for (; i >= 0; i -= STRIDE4) {
            float4 a = x4[i];
            mn0 = fminf(mn0, fminf(fminf(a.x, a.y), fminf(a.z, a.w)));
            mx0 = fmaxf(mx0, fmaxf(fmaxf(a.x, a.y), fmaxf(a.z, a.w)));
        }
        float vmin = fminf(mn0, mn1);
        float vmax = fmaxf(mx0, mx1);

        #pragma unroll
        for (int o = 16; o > 0; o >>= 1) {
            vmin = fminf(vmin, __shfl_xor_sync(0xFFFFFFFFu, vmin, o));
            vmax = fmaxf(vmax, __shfl_xor_sync(0xFFFFFFFFu, vmax, o));
        }
        int warp = tid >> 5;
        if ((tid & 31) == 0) { s_red[warp] = vmin; }
        __syncthreads();
        if (warp == 0 && (tid & 31) < 8) { /* keep vmin reduce simple below */ }
        if (tid == 0) {
            #pragma unroll
            for (int w = 1; w < 8; w++) vmin = fminf(vmin, s_red[w]);
            s_min = vmin;                       // stash block min temporarily
        }
        __syncthreads();
        if ((tid & 31) == 0) { s_red[warp] = vmax; }
        __syncthreads();

        // ---------------- Device-wide barrier (thread 0) ----------------
        if (tid == 0) {
            #pragma unroll
            for (int w = 1; w < 8; w++) vmax = fmaxf(vmax, s_red[w]);
            vmin = s_min;

            unsigned my_gen = *(volatile unsigned int*)&g_gen;  // read BEFORE arrival
            atomicMin(&g_min_enc, enc_f(vmin));
            atomicMax(&g_max_enc, enc_f(vmax));
            __threadfence();
            unsigned old = atomicAdd(&g_count, 1u);
            if (old == (unsigned)(GRID_X - 1)) {
                // last to arrive: finalize + reset + release
                g_min_f = dec_f(g_min_enc);
                g_max_f = dec_f(g_max_enc);
                g_min_enc = ENC_MIN_INIT;
                g_max_enc = ENC_MAX_INIT;
                g_count   = 0;
                __threadfence();
                atomicAdd(&g_gen, 1u);
            } else {
                while (*(volatile unsigned int*)&g_gen == my_gen) { __nanosleep(64); }
                __threadfence();   // acquire
            }
            s_min = *(volatile float*)&g_min_f;
            s_max = *(volatile float*)&g_max_f;
        }
        __syncthreads();
    }

    // ---------------- Phase 2: weighted-histogram reduction ----------------
    const float xmin = s_min;
    const float xmax = s_max;
    const float delta     = __fdiv_rn(__fsub_rn(xmax, xmin), (float)BINS);
    const float inv_delta = 1.0f / delta;
    const float c0        = -xmin * inv_delta;
    const float MAGIC     = 12582912.0f;  // 1.5 * 2^23
    const float EPS       = 1.0e-4f;
    const int   lane      = tid & 31;
    const int   warp      = tid >> 5;

    for (int nc = blockIdx.x; nc < NN * CC; nc += GRID_X) {
        const int c = nc & (CC - 1);
        const float co_lane = __ldg(coeff + c * BINS + lane);
        const float4* xp = reinterpret_cast<const float4*>(x + (size_t)nc * HWSZ);

        float acc = 0.0f;
        #pragma unroll 4
        for (int j = 0; j < HWSZ / (BLOCK_X * 4); j += 2) {
            float4 a  = xp[tid + j * BLOCK_X];
            float4 b4 = xp[tid + (j + 1) * BLOCK_X];
            float vs[8] = {a.x, a.y, a.z, a.w, b4.x, b4.y, b4.z, b4.w};
            int   bs[8];
            bool  nearEdge = false;
            #pragma unroll
            for (int k = 0; k < 8; k++) {
                float r  = fmaf(vs[k], inv_delta, c0);
                float f  = r + MAGIC;
                int   bi = __float_as_int(f) - 0x4B400000;
                float d  = r - (f - MAGIC);
                bs[k] = (d < 0.0f) ? bi - 1 : bi;     // floor(r)
                nearEdge = nearEdge || (fabsf(d) < EPS);
            }
            if (__any_sync(0xFFFFFFFFu, nearEdge)) {  // rare, warp-uniform
                #pragma unroll
                for (int k = 0; k < 8; k++)
                    bs[k] = bin_exact(vs[k], xmin, delta);
            }
            #pragma unroll
            for (int k = 0; k < 8; k++) {
                float co = __shfl_sync(0xFFFFFFFFu, co_lane, bs[k]);
                float th;
                asm("tanh.approx.f32 %0, %1;" : "=f"(th) : "f"(vs[k]));
                acc = fmaf(th, co, acc);
            }
        }

        #pragma unroll
        for (int o = 16; o > 0; o >>= 1)
            acc += __shfl_xor_sync(0xFFFFFFFFu, acc, o);

        __syncthreads();                 // protect s_red reuse across slices
        if (lane == 0) s_red[warp] = acc;
        __syncthreads();
        if (tid == 0) {
            float t = s_red[0];
            #pragma unroll
            for (int w = 1; w < 8; w++) t += s_red[w];
            out[nc] = t;
        }
    }
}

// ---------------------------------------------------------------------------
extern "C" void kernel_launch(void* const* d_in, const int* in_sizes, int n_in,
                              void* d_out, int out_size) {
    const float* x     = (const float*)d_in[0];
    const float* coeff = (const float*)d_in[1];
    float*       out   = (float*)d_out;

    hp_fused_kernel<<<GRID_X, BLOCK_X>>>(x, coeff, out);
}